// round 10
// baseline (speedup 1.0000x reference)
#include <cuda_runtime.h>

#define NN  69
#define BB  32
#define TT  1024
#define FIN 8
#define H1  32
#define H2  16
#define TW  8      // t-positions per block (lane = t*4 + chunk)
#define XS  12     // x row stride (floats): slab 69*48B = 112 mod 128 -> bank-tiling
#define YS  12     // y row stride (floats): same tiling
#define PS  20     // p row stride (floats): slab 69*80B = 96 mod 128 -> bank-tiling
#define NTASK (TW * NN)   // 552

typedef unsigned long long u64;

// ---- f32x2 helpers (Blackwell packed fp32) --------------------------------
__device__ __forceinline__ void ffma2(u64& d, u64 a, u64 b) {
    asm("fma.rn.f32x2 %0, %1, %2, %0;" : "+l"(d) : "l"(a), "l"(b));
}
__device__ __forceinline__ u64 dup2(float a) {
    u64 r; asm("mov.b64 %0, {%1, %1};" : "=l"(r) : "f"(a)); return r;
}
__device__ __forceinline__ u64 pack2(float a, float b) {
    u64 r; asm("mov.b64 %0, {%1, %2};" : "=l"(r) : "f"(a), "f"(b)); return r;
}
__device__ __forceinline__ void unpack2(u64 v, float& a, float& b) {
    asm("mov.b64 {%0, %1}, %2;" : "=f"(a), "=f"(b) : "l"(v));
}

// ---- scratch (no cudaMalloc allowed) --------------------------------------
__device__ float2 g_ell[NN * NN];      // (val, int_as_float(col)) per row, packed
__device__ int    g_cnt[NN];
__device__ float2 g_W2t[H2 * 16];      // [c][j2] = (W2[2j2][c], W2[2j2+1][c])

// ---------------------------------------------------------------------------
// Prep: adj_n = D^-1/2 (A+I) D^-1/2 packed ELL (val+col in one float2) + W2t.
// ---------------------------------------------------------------------------
__global__ void prep_kernel(const float* __restrict__ adj,
                            const float* __restrict__ W2) {
    __shared__ float dis[NN];
    int tid = threadIdx.x;
    if (tid < NN) {
        float d = 1.0f;
        for (int m = 0; m < NN; m++) d += adj[tid * NN + m];
        dis[tid] = rsqrtf(d);
    }
    __syncthreads();
    if (tid < NN) {
        float di = dis[tid];
        int cnt = 0;
        for (int m = 0; m < NN; m++) {
            float v = adj[tid * NN + m];
            if (m == tid) v += 1.0f;
            if (v != 0.0f) {
                g_ell[tid * NN + cnt] =
                    make_float2(v * di * dis[m], __int_as_float(m));
                cnt++;
            }
        }
        g_cnt[tid] = cnt;
    }
    if (tid < H2 * 16) {
        int c = tid >> 4, j2 = tid & 15;
        g_W2t[tid] = make_float2(W2[(2 * j2) * H2 + c], W2[(2 * j2 + 1) * H2 + c]);
    }
}

// ---------------------------------------------------------------------------
// Fused GCN. Aggregations: warp<->n, lane<->(t,chunk): adjacency broadcast,
// bank-tiled gathers at the wavefront floor. FC: thread<->(t,n), f32x2 regs.
// ---------------------------------------------------------------------------
__global__ __launch_bounds__(256, 1)
void gcn_kernel(const float* __restrict__ x,
                const float* __restrict__ W1,
                float* __restrict__ out) {
    extern __shared__ float sm[];
    float*  s_W1  = sm;                            // 256 floats ([8][32] row-major)
    float2* s_W2t = (float2*)(sm + 256);           // 256 float2
    float*  s_x   = sm + 256 + 512;                // TW*NN*XS = 6624
    float*  s_y   = s_x + TW * NN * XS;            // TW*NN*YS = 6624
    float*  s_p   = s_y + TW * NN * YS;            // TW*NN*PS = 11040
    float2* s_ell = (float2*)(s_p + TW * NN * PS); // 4761 float2 (8B aligned)
    int*    s_cnt = (int*)(s_ell + NN * NN);       // 69 ints

    const int tid = threadIdx.x;
    const int bt0 = blockIdx.x * TW;
    const int b   = bt0 >> 10;
    const int t0  = bt0 & (TT - 1);

    // ---- cooperative smem fill ----
    s_W1[tid]  = W1[tid];                      // exactly 256 floats
    s_W2t[tid] = g_W2t[tid];                   // exactly 256 float2
    {
        const u64* ge = (const u64*)g_ell;
        u64* se = (u64*)s_ell;
        for (int i = tid; i < NN * NN; i += 256) se[i] = ge[i];
    }
    if (tid < NN) s_cnt[tid] = g_cnt[tid];
    {   // x slab: [n][b][t0+t][f] -> s_x[t][n][0..7] (stride XS), float4 moves
        const float4* xg = (const float4*)x;
        for (int i = tid; i < NN * TW * 2; i += 256) {
            int n = i >> 4;
            int r = i & 15;
            int t = r >> 1, h = r & 1;
            float4 v = xg[((size_t)(n * BB + b) * TT + t0 + t) * 2 + h];
            *(float4*)(s_x + (t * NN + n) * XS + h * 4) = v;
        }
    }
    __syncthreads();

    const int w    = tid >> 5;
    const int lane = tid & 31;
    const int tl   = lane >> 2;      // t of this lane (0..7)
    const int cq   = lane & 3;       // chunk of this lane (0..3)

    // =========== Phase A: agg1. warp<->n; lane reads x[tl][m][cq*2..+1] ====
    {
        const float* xbase = s_x + tl * (NN * XS) + cq * 2;
        float* ybase = s_y + tl * (NN * YS) + cq * 2;
        for (int n = w; n < NN; n += 8) {
            const float2* ell = s_ell + n * NN;   // broadcast reads
            const int cnt = s_cnt[n];
            u64 acc = 0ull;
            int k = 0;
            for (; k + 2 <= cnt; k += 2) {
                float2 e0 = ell[k], e1 = ell[k + 1];
                u64 v0 = *(const u64*)(xbase + __float_as_int(e0.y) * XS);
                u64 v1 = *(const u64*)(xbase + __float_as_int(e1.y) * XS);
                ffma2(acc, dup2(e0.x), v0);
                ffma2(acc, dup2(e1.x), v1);
            }
            if (k < cnt) {
                float2 e0 = ell[k];
                u64 v0 = *(const u64*)(xbase + __float_as_int(e0.y) * XS);
                ffma2(acc, dup2(e0.x), v0);
            }
            *(u64*)(ybase + n * YS) = acc;
        }
    }
    __syncthreads();

    // =========== Phase A2: per (t,n): FC1 relu FC2 -> p (registers) ========
    #pragma unroll 1
    for (int r = 0; r < 3; r++) {
        int i = tid + (r << 8);
        if (i < NTASK) {
            int t = i / NN;
            int n = i - t * NN;

            // ---- load y[8] ----
            const ulonglong2* yr = (const ulonglong2*)(s_y + (t * NN + n) * YS);
            ulonglong2 ya = yr[0], yb = yr[1];
            float ys[8];
            unpack2(ya.x, ys[0], ys[1]); unpack2(ya.y, ys[2], ys[3]);
            unpack2(yb.x, ys[4], ys[5]); unpack2(yb.y, ys[6], ys[7]);

            // ---- FC1: h[32] = y[8] @ W1 (broadcast weights) ----
            u64 h[16];
            #pragma unroll
            for (int q = 0; q < 16; q++) h[q] = 0ull;
            #pragma unroll
            for (int f = 0; f < FIN; f++) {
                u64 yd = dup2(ys[f]);
                const ulonglong2* wr = (const ulonglong2*)(s_W1 + f * H1);
                #pragma unroll
                for (int q = 0; q < 8; q++) {
                    ulonglong2 wv = wr[q];
                    ffma2(h[2 * q],     yd, wv.x);
                    ffma2(h[2 * q + 1], yd, wv.y);
                }
            }
            #pragma unroll
            for (int q = 0; q < 16; q++) {
                float a, bb2; unpack2(h[q], a, bb2);
                h[q] = pack2(fmaxf(a, 0.0f), fmaxf(bb2, 0.0f));
            }

            // ---- FC2: p[16] = h @ W2 ----
            float p[H2];
            #pragma unroll
            for (int c = 0; c < H2; c++) {
                u64 acc = 0ull;
                const ulonglong2* w2r = (const ulonglong2*)(s_W2t + c * 16);
                #pragma unroll
                for (int q = 0; q < 8; q++) {
                    ulonglong2 wv = w2r[q];
                    ffma2(acc, h[2 * q],     wv.x);
                    ffma2(acc, h[2 * q + 1], wv.y);
                }
                float a, bb2; unpack2(acc, a, bb2);
                p[c] = a + bb2;
            }

            float* pr = s_p + (t * NN + n) * PS;
            *(float4*)(pr)      = make_float4(p[0],  p[1],  p[2],  p[3]);
            *(float4*)(pr + 4)  = make_float4(p[4],  p[5],  p[6],  p[7]);
            *(float4*)(pr + 8)  = make_float4(p[8],  p[9],  p[10], p[11]);
            *(float4*)(pr + 12) = make_float4(p[12], p[13], p[14], p[15]);
        }
    }
    __syncthreads();

    // =========== Phase B: agg2 + sigmoid. warp<->n; lane = (tl, cq) ========
    {
        const float* pbase = s_p + tl * (NN * PS) + cq * 4;
        for (int n = w; n < NN; n += 8) {
            const float2* ell = s_ell + n * NN;
            const int cnt = s_cnt[n];
            u64 z0 = 0ull, z1 = 0ull;
            int k = 0;
            for (; k + 2 <= cnt; k += 2) {
                float2 e0 = ell[k], e1 = ell[k + 1];
                ulonglong2 v0 = *(const ulonglong2*)(pbase + __float_as_int(e0.y) * PS);
                ulonglong2 v1 = *(const ulonglong2*)(pbase + __float_as_int(e1.y) * PS);
                u64 a0 = dup2(e0.x), a1 = dup2(e1.x);
                ffma2(z0, a0, v0.x); ffma2(z1, a0, v0.y);
                ffma2(z0, a1, v1.x); ffma2(z1, a1, v1.y);
            }
            if (k < cnt) {
                float2 e0 = ell[k];
                ulonglong2 v0 = *(const ulonglong2*)(pbase + __float_as_int(e0.y) * PS);
                u64 a0 = dup2(e0.x);
                ffma2(z0, a0, v0.x); ffma2(z1, a0, v0.y);
            }

            float za, zb, zc, zd;
            unpack2(z0, za, zb); unpack2(z1, zc, zd);
            float4 o;
            o.x = 1.0f / (1.0f + __expf(-za));
            o.y = 1.0f / (1.0f + __expf(-zb));
            o.z = 1.0f / (1.0f + __expf(-zc));
            o.w = 1.0f / (1.0f + __expf(-zd));

            *(float4*)(out + (((size_t)b * TT + t0 + tl) * NN + n) * H2 + cq * 4) = o;
        }
    }
}

// ---------------------------------------------------------------------------
extern "C" void kernel_launch(void* const* d_in, const int* in_sizes, int n_in,
                              void* d_out, int out_size) {
    const float* x   = (const float*)d_in[0];   // [69, 32, 1024, 8]
    const float* adj = (const float*)d_in[1];   // [69, 69]
    const float* W1  = (const float*)d_in[2];   // [8, 32]
    const float* W2  = (const float*)d_in[3];   // [32, 16]
    float* out = (float*)d_out;                 // [32, 1024, 69, 16]

    prep_kernel<<<1, 256>>>(adj, W2);

    const int smem_bytes =
        (256 + 512 + TW * NN * XS + TW * NN * YS + TW * NN * PS) * 4  // floats
        + NN * NN * 8      // ell float2
        + NN * 4;          // cnt
    cudaFuncSetAttribute(gcn_kernel,
                         cudaFuncAttributeMaxDynamicSharedMemorySize, smem_bytes);
    gcn_kernel<<<(BB * TT) / TW, 256, smem_bytes>>>(x, W1, out);
}

// round 11
// speedup vs baseline: 1.7433x; 1.7433x over previous
#include <cuda_runtime.h>

#define NN  69
#define BB  32
#define TT  1024
#define FIN 8
#define H1  32
#define H2  16
#define TW  8      // t-positions per block
#define XS  8      // x row stride: slab 69*32B % 128 = 32 -> phase-conflict-free
#define YS  8      // y row stride: same
#define PS  16     // p row stride: slab 69*64B % 128 = 64 -> phase-conflict-free
#define ELLS 70    // ELL row stride (entries), 16B-aligned rows, even-padded
#define NTASK (TW * NN)   // 552

typedef unsigned long long u64;

// ---- f32x2 helpers (Blackwell packed fp32) --------------------------------
__device__ __forceinline__ void ffma2(u64& d, u64 a, u64 b) {
    asm("fma.rn.f32x2 %0, %1, %2, %0;" : "+l"(d) : "l"(a), "l"(b));
}
__device__ __forceinline__ u64 dup2(float a) {
    u64 r; asm("mov.b64 %0, {%1, %1};" : "=l"(r) : "f"(a)); return r;
}
__device__ __forceinline__ u64 pack2(float a, float b) {
    u64 r; asm("mov.b64 %0, {%1, %2};" : "=l"(r) : "f"(a), "f"(b)); return r;
}
__device__ __forceinline__ void unpack2(u64 v, float& a, float& b) {
    asm("mov.b64 {%0, %1}, %2;" : "=f"(a), "=f"(b) : "l"(v));
}

// ---- scratch (no cudaMalloc allowed) --------------------------------------
__device__ float2 g_ell[NN * ELLS];    // (val, int_as_float(col)), even-padded
__device__ int    g_cnt[NN];           // padded-even counts
__device__ float2 g_W2t[H2 * 16];      // [c][j2] = (W2[2j2][c], W2[2j2+1][c])

// ---------------------------------------------------------------------------
// Prep: adj_n = D^-1/2 (A+I) D^-1/2 packed ELL + W2 pair-transpose.
// ---------------------------------------------------------------------------
__global__ void prep_kernel(const float* __restrict__ adj,
                            const float* __restrict__ W2) {
    __shared__ float dis[NN];
    int tid = threadIdx.x;
    if (tid < NN) {
        float d = 1.0f;
        for (int m = 0; m < NN; m++) d += adj[tid * NN + m];
        dis[tid] = rsqrtf(d);
    }
    __syncthreads();
    if (tid < NN) {
        float di = dis[tid];
        int cnt = 0;
        for (int m = 0; m < NN; m++) {
            float v = adj[tid * NN + m];
            if (m == tid) v += 1.0f;
            if (v != 0.0f) {
                g_ell[tid * ELLS + cnt] =
                    make_float2(v * di * dis[m], __int_as_float(m));
                cnt++;
            }
        }
        if (cnt & 1) {   // pad to even with a zero entry (col 0 is safe)
            g_ell[tid * ELLS + cnt] = make_float2(0.0f, __int_as_float(0));
            cnt++;
        }
        g_cnt[tid] = cnt;
    }
    if (tid < H2 * 16) {
        int c = tid >> 4, j2 = tid & 15;
        g_W2t[tid] = make_float2(W2[(2 * j2) * H2 + c], W2[(2 * j2 + 1) * H2 + c]);
    }
}

// ---------------------------------------------------------------------------
// Fused GCN. Aggregations: warp<->n, lane<->(t,chunk), adjacency broadcast,
// phase-conflict-free gathers. FC: thread<->(t,n) in f32x2 registers.
// p aliases x (disjoint lifetimes) -> 94.9KB smem -> 2 blocks/SM.
// ---------------------------------------------------------------------------
__global__ __launch_bounds__(256, 2)
void gcn_kernel(const float* __restrict__ x,
                const float* __restrict__ W1,
                float* __restrict__ out) {
    extern __shared__ float sm[];
    float*  s_W1  = sm;                            // 256 floats ([8][32])
    float2* s_W2t = (float2*)(sm + 256);           // 256 float2
    float*  s_xp  = sm + 768;                      // x: TW*NN*XS=4416 | p: TW*NN*PS=8832 (alias)
    float*  s_y   = s_xp + TW * NN * PS;           // TW*NN*YS = 4416
    float*  s_ell = s_y + TW * NN * YS;            // NN*ELLS float2 = 9660 floats
    int*    s_cnt = (int*)(s_ell + NN * ELLS * 2); // 69 ints

    const int tid = threadIdx.x;
    const int bt0 = blockIdx.x * TW;
    const int b   = bt0 >> 10;
    const int t0  = bt0 & (TT - 1);

    // ---- cooperative smem fill ----
    s_W1[tid]  = W1[tid];
    s_W2t[tid] = g_W2t[tid];
    {
        const u64* ge = (const u64*)g_ell;
        u64* se = (u64*)s_ell;
        for (int i = tid; i < NN * ELLS; i += 256) se[i] = ge[i];
    }
    if (tid < NN) s_cnt[tid] = g_cnt[tid];
    {   // x slab: [n][b][t0+t][f] -> s_xp[t][n][0..7] (stride XS=8)
        const float4* xg = (const float4*)x;
        for (int i = tid; i < NN * TW * 2; i += 256) {
            int n = i >> 4;
            int r = i & 15;
            int t = r >> 1, h = r & 1;
            float4 v = xg[((size_t)(n * BB + b) * TT + t0 + t) * 2 + h];
            *(float4*)(s_xp + (t * NN + n) * XS + h * 4) = v;
        }
    }
    __syncthreads();

    const int w    = tid >> 5;
    const int lane = tid & 31;
    const int tl   = lane >> 2;      // t of this lane (0..7)
    const int cq   = lane & 3;       // chunk of this lane (0..3)

    // =========== Phase A: agg1. warp<->n; lane reads x[tl][m][cq*2..+1] ====
    {
        const float* xbase = s_xp + tl * (NN * XS) + cq * 2;
        float* ybase = s_y + tl * (NN * YS) + cq * 2;
        for (int n = w; n < NN; n += 8) {
            const float4* ell4 = (const float4*)(s_ell + n * (ELLS * 2));
            const int cnt = s_cnt[n];   // even
            u64 acc = 0ull;
            for (int k = 0; k < cnt; k += 2) {
                float4 e = ell4[k >> 1];               // broadcast, 1 wf / 2 nbrs
                u64 v0 = *(const u64*)(xbase + __float_as_int(e.y) * XS);
                u64 v1 = *(const u64*)(xbase + __float_as_int(e.w) * XS);
                ffma2(acc, dup2(e.x), v0);
                ffma2(acc, dup2(e.z), v1);
            }
            *(u64*)(ybase + n * YS) = acc;
        }
    }
    __syncthreads();

    // =========== Phase A2: per (t,n): FC1 relu FC2 -> p (registers) ========
    // (x slab is dead now; p overwrites the same region with stride PS)
    #pragma unroll 1
    for (int r = 0; r < 3; r++) {
        int i = tid + (r << 8);
        if (i < NTASK) {
            int t = i / NN;
            int n = i - t * NN;

            const ulonglong2* yr = (const ulonglong2*)(s_y + (t * NN + n) * YS);
            ulonglong2 ya = yr[0], yb = yr[1];
            float ys[8];
            unpack2(ya.x, ys[0], ys[1]); unpack2(ya.y, ys[2], ys[3]);
            unpack2(yb.x, ys[4], ys[5]); unpack2(yb.y, ys[6], ys[7]);

            // ---- FC1: h[32] = y[8] @ W1 (broadcast weights) ----
            u64 h[16];
            #pragma unroll
            for (int q = 0; q < 16; q++) h[q] = 0ull;
            #pragma unroll
            for (int f = 0; f < FIN; f++) {
                u64 yd = dup2(ys[f]);
                const ulonglong2* wr = (const ulonglong2*)(s_W1 + f * H1);
                #pragma unroll
                for (int q = 0; q < 8; q++) {
                    ulonglong2 wv = wr[q];
                    ffma2(h[2 * q],     yd, wv.x);
                    ffma2(h[2 * q + 1], yd, wv.y);
                }
            }
            #pragma unroll
            for (int q = 0; q < 16; q++) {
                float a, bb2; unpack2(h[q], a, bb2);
                h[q] = pack2(fmaxf(a, 0.0f), fmaxf(bb2, 0.0f));
            }

            // ---- FC2: p[16] = h @ W2 ----
            float p[H2];
            #pragma unroll
            for (int c = 0; c < H2; c++) {
                u64 acc = 0ull;
                const ulonglong2* w2r = (const ulonglong2*)(s_W2t + c * 16);
                #pragma unroll
                for (int q = 0; q < 8; q++) {
                    ulonglong2 wv = w2r[q];
                    ffma2(acc, h[2 * q],     wv.x);
                    ffma2(acc, h[2 * q + 1], wv.y);
                }
                float a, bb2; unpack2(acc, a, bb2);
                p[c] = a + bb2;
            }

            float* pr = s_xp + (t * NN + n) * PS;
            *(float4*)(pr)      = make_float4(p[0],  p[1],  p[2],  p[3]);
            *(float4*)(pr + 4)  = make_float4(p[4],  p[5],  p[6],  p[7]);
            *(float4*)(pr + 8)  = make_float4(p[8],  p[9],  p[10], p[11]);
            *(float4*)(pr + 12) = make_float4(p[12], p[13], p[14], p[15]);
        }
    }
    __syncthreads();

    // =========== Phase B: agg2 + sigmoid. warp<->n; lane = (tl, cq) ========
    {
        const float* pbase = s_xp + tl * (NN * PS) + cq * 4;
        for (int n = w; n < NN; n += 8) {
            const float4* ell4 = (const float4*)(s_ell + n * (ELLS * 2));
            const int cnt = s_cnt[n];
            u64 z0 = 0ull, z1 = 0ull;
            for (int k = 0; k < cnt; k += 2) {
                float4 e = ell4[k >> 1];
                ulonglong2 v0 = *(const ulonglong2*)(pbase + __float_as_int(e.y) * PS);
                ulonglong2 v1 = *(const ulonglong2*)(pbase + __float_as_int(e.w) * PS);
                u64 a0 = dup2(e.x), a1 = dup2(e.z);
                ffma2(z0, a0, v0.x); ffma2(z1, a0, v0.y);
                ffma2(z0, a1, v1.x); ffma2(z1, a1, v1.y);
            }

            float za, zb, zc, zd;
            unpack2(z0, za, zb); unpack2(z1, zc, zd);
            float4 o;
            o.x = 1.0f / (1.0f + __expf(-za));
            o.y = 1.0f / (1.0f + __expf(-zb));
            o.z = 1.0f / (1.0f + __expf(-zc));
            o.w = 1.0f / (1.0f + __expf(-zd));

            *(float4*)(out + (((size_t)b * TT + t0 + tl) * NN + n) * H2 + cq * 4) = o;
        }
    }
}

// ---------------------------------------------------------------------------
extern "C" void kernel_launch(void* const* d_in, const int* in_sizes, int n_in,
                              void* d_out, int out_size) {
    const float* x   = (const float*)d_in[0];   // [69, 32, 1024, 8]
    const float* adj = (const float*)d_in[1];   // [69, 69]
    const float* W1  = (const float*)d_in[2];   // [8, 32]
    const float* W2  = (const float*)d_in[3];   // [32, 16]
    float* out = (float*)d_out;                 // [32, 1024, 69, 16]

    prep_kernel<<<1, 256>>>(adj, W2);

    const int smem_bytes =
        (768 + TW * NN * PS + TW * NN * YS) * 4   // W1/W2t + x|p alias + y
        + NN * ELLS * 8                           // ell float2
        + NN * 4;                                 // cnt
    cudaFuncSetAttribute(gcn_kernel,
                         cudaFuncAttributeMaxDynamicSharedMemorySize, smem_bytes);
    gcn_kernel<<<(BB * TT) / TW, 256, smem_bytes>>>(x, W1, out);
}

// round 12
// speedup vs baseline: 1.8085x; 1.0374x over previous
#include <cuda_runtime.h>
#include <cuda_fp16.h>

#define NN  69
#define BB  32
#define TT  1024
#define FIN 8
#define H1  32
#define H2  16
#define TW  8      // t-positions per block
#define XSH 8      // x row stride in halves (16B rows): slab 1104B % 128 = 80 -> CF
#define YS  8      // y row stride in floats (32B rows): slab 2208B % 128 = 32 -> CF
#define PSH 16     // p row stride in halves (32B rows): slab 2208B % 128 = 32 -> CF
#define ELLS 70    // ELL row stride (entries), 16B rows, even-padded
#define NTASK (TW * NN)   // 552

typedef unsigned long long u64;

// ---- f32x2 helpers (Blackwell packed fp32) --------------------------------
__device__ __forceinline__ void ffma2(u64& d, u64 a, u64 b) {
    asm("fma.rn.f32x2 %0, %1, %2, %0;" : "+l"(d) : "l"(a), "l"(b));
}
__device__ __forceinline__ u64 dup2(float a) {
    u64 r; asm("mov.b64 %0, {%1, %1};" : "=l"(r) : "f"(a)); return r;
}
__device__ __forceinline__ u64 pack2(float a, float b) {
    u64 r; asm("mov.b64 %0, {%1, %2};" : "=l"(r) : "f"(a), "f"(b)); return r;
}
__device__ __forceinline__ void unpack2(u64 v, float& a, float& b) {
    asm("mov.b64 {%0, %1}, %2;" : "=f"(a), "=f"(b) : "l"(v));
}
__device__ __forceinline__ u64 h2_to_f2(unsigned h) {
    float2 f = __half22float2(*(const __half2*)&h);
    return pack2(f.x, f.y);
}

// ---- scratch (no cudaMalloc allowed) --------------------------------------
__device__ float2 g_ell[NN * ELLS];    // (val, int_as_float(col)), even-padded
__device__ int    g_cnt[NN];           // padded-even counts
__device__ float2 g_W2t[H2 * 16];      // [c][j2] = (W2[2j2][c], W2[2j2+1][c])

// ---------------------------------------------------------------------------
// Prep: adj_n = D^-1/2 (A+I) D^-1/2 packed ELL + W2 pair-transpose.
// ---------------------------------------------------------------------------
__global__ void prep_kernel(const float* __restrict__ adj,
                            const float* __restrict__ W2) {
    __shared__ float dis[NN];
    int tid = threadIdx.x;
    if (tid < NN) {
        float d = 1.0f;
        for (int m = 0; m < NN; m++) d += adj[tid * NN + m];
        dis[tid] = rsqrtf(d);
    }
    __syncthreads();
    if (tid < NN) {
        float di = dis[tid];
        int cnt = 0;
        for (int m = 0; m < NN; m++) {
            float v = adj[tid * NN + m];
            if (m == tid) v += 1.0f;
            if (v != 0.0f) {
                g_ell[tid * ELLS + cnt] =
                    make_float2(v * di * dis[m], __int_as_float(m));
                cnt++;
            }
        }
        if (cnt & 1) {   // pad to even with a zero entry
            g_ell[tid * ELLS + cnt] = make_float2(0.0f, __int_as_float(0));
            cnt++;
        }
        g_cnt[tid] = cnt;
    }
    if (tid < H2 * 16) {
        int c = tid >> 4, j2 = tid & 15;
        g_W2t[tid] = make_float2(W2[(2 * j2) * H2 + c], W2[(2 * j2 + 1) * H2 + c]);
    }
}

// ---------------------------------------------------------------------------
// Fused GCN. Gathered operands (x, p) stored fp16 in smem -> half the gather
// wavefronts; all accumulation fp32 (f32x2). Aggregations: warp<->n,
// lane<->(t,chunk), adjacency broadcast. FC: thread<->(t,n), f32x2 regs.
// p aliases x region (disjoint lifetimes). 77.3KB smem -> 2 blocks/SM.
// ---------------------------------------------------------------------------
__global__ __launch_bounds__(256, 2)
void gcn_kernel(const float* __restrict__ x,
                const float* __restrict__ W1,
                float* __restrict__ out) {
    extern __shared__ float sm[];
    float*  s_W1  = sm;                              // 1024B
    float2* s_W2t = (float2*)(sm + 256);             // 2048B -> ends 3072
    float*  s_ell = sm + 768;                        // NN*ELLS float2 = 38640B
    __half* s_xp  = (__half*)(s_ell + NN * ELLS * 2);// x: 8832B | p: 17664B (alias)
    float*  s_y   = (float*)(s_xp + TW * NN * PSH);  // 17664B
    int*    s_cnt = (int*)(s_y + TW * NN * YS);      // 276B

    const int tid = threadIdx.x;
    const int bt0 = blockIdx.x * TW;
    const int b   = bt0 >> 10;
    const int t0  = bt0 & (TT - 1);

    // ---- cooperative smem fill ----
    s_W1[tid] = W1[tid];
    ((float2*)s_W2t)[tid] = g_W2t[tid];
    {
        const u64* ge = (const u64*)g_ell;
        u64* se = (u64*)s_ell;
        for (int i = tid; i < NN * ELLS; i += 256) se[i] = ge[i];
    }
    if (tid < NN) s_cnt[tid] = g_cnt[tid];
    {   // x slab: [n][b][t0+t][f] -> s_xp half [t][n][0..7] (stride XSH=8)
        const float4* xg = (const float4*)x;
        for (int i = tid; i < NN * TW * 2; i += 256) {
            int n = i >> 4;
            int r = i & 15;
            int t = r >> 1, h = r & 1;
            float4 v = xg[((size_t)(n * BB + b) * TT + t0 + t) * 2 + h];
            __half2 h0 = __floats2half2_rn(v.x, v.y);
            __half2 h1 = __floats2half2_rn(v.z, v.w);
            uint2 pkt = make_uint2(*(unsigned*)&h0, *(unsigned*)&h1);
            *(uint2*)(s_xp + (t * NN + n) * XSH + h * 4) = pkt;
        }
    }
    __syncthreads();

    const int w    = tid >> 5;
    const int lane = tid & 31;
    const int tl   = lane >> 2;      // t of this lane (0..7)
    const int cq   = lane & 3;       // chunk of this lane (0..3)

    // =========== Phase A: agg1. warp<->n; lane: x_h[tl][m][cq*2..+1] =======
    {
        const __half* xbase = s_xp + tl * (NN * XSH) + cq * 2;
        float* ybase = s_y + tl * (NN * YS) + cq * 2;
        for (int n = w; n < NN; n += 8) {
            const float4* ell4 = (const float4*)(s_ell + n * (ELLS * 2));
            const int cnt = s_cnt[n];   // even
            u64 acc = 0ull;
            for (int k = 0; k < cnt; k += 2) {
                float4 e = ell4[k >> 1];               // broadcast, 2 nbrs
                unsigned r0 = *(const unsigned*)(xbase + __float_as_int(e.y) * XSH);
                unsigned r1 = *(const unsigned*)(xbase + __float_as_int(e.w) * XSH);
                ffma2(acc, dup2(e.x), h2_to_f2(r0));
                ffma2(acc, dup2(e.z), h2_to_f2(r1));
            }
            *(u64*)(ybase + n * YS) = acc;
        }
    }
    __syncthreads();

    // =========== Phase A2: per (t,n): FC1 relu FC2 -> p fp16 (registers) ===
    #pragma unroll 1
    for (int r = 0; r < 3; r++) {
        int i = tid + (r << 8);
        if (i < NTASK) {
            int t = i / NN;
            int n = i - t * NN;

            const ulonglong2* yr = (const ulonglong2*)(s_y + (t * NN + n) * YS);
            ulonglong2 ya = yr[0], yb = yr[1];
            float ys[8];
            unpack2(ya.x, ys[0], ys[1]); unpack2(ya.y, ys[2], ys[3]);
            unpack2(yb.x, ys[4], ys[5]); unpack2(yb.y, ys[6], ys[7]);

            // ---- FC1: h[32] = y[8] @ W1 (broadcast weights) ----
            u64 h[16];
            #pragma unroll
            for (int q = 0; q < 16; q++) h[q] = 0ull;
            #pragma unroll
            for (int f = 0; f < FIN; f++) {
                u64 yd = dup2(ys[f]);
                const ulonglong2* wr = (const ulonglong2*)(s_W1 + f * H1);
                #pragma unroll
                for (int q = 0; q < 8; q++) {
                    ulonglong2 wv = wr[q];
                    ffma2(h[2 * q],     yd, wv.x);
                    ffma2(h[2 * q + 1], yd, wv.y);
                }
            }
            #pragma unroll
            for (int q = 0; q < 16; q++) {
                float a, bb2; unpack2(h[q], a, bb2);
                h[q] = pack2(fmaxf(a, 0.0f), fmaxf(bb2, 0.0f));
            }

            // ---- FC2: p[16] = h @ W2 ----
            float p[H2];
            #pragma unroll
            for (int c = 0; c < H2; c++) {
                u64 acc = 0ull;
                const ulonglong2* w2r = (const ulonglong2*)(s_W2t + c * 16);
                #pragma unroll
                for (int q = 0; q < 8; q++) {
                    ulonglong2 wv = w2r[q];
                    ffma2(acc, h[2 * q],     wv.x);
                    ffma2(acc, h[2 * q + 1], wv.y);
                }
                float a, bb2; unpack2(acc, a, bb2);
                p[c] = a + bb2;
            }

            // ---- store p as fp16 (2x 16B stores) ----
            unsigned hp[8];
            #pragma unroll
            for (int q = 0; q < 8; q++) {
                __half2 hv = __floats2half2_rn(p[2 * q], p[2 * q + 1]);
                hp[q] = *(unsigned*)&hv;
            }
            __half* pr = s_xp + (t * NN + n) * PSH;
            *(uint4*)(pr)     = make_uint4(hp[0], hp[1], hp[2], hp[3]);
            *(uint4*)(pr + 8) = make_uint4(hp[4], hp[5], hp[6], hp[7]);
        }
    }
    __syncthreads();

    // =========== Phase B: agg2 + sigmoid. warp<->n; lane = (tl, cq) ========
    {
        const __half* pbase = s_xp + tl * (NN * PSH) + cq * 4;
        for (int n = w; n < NN; n += 8) {
            const float4* ell4 = (const float4*)(s_ell + n * (ELLS * 2));
            const int cnt = s_cnt[n];
            u64 z0 = 0ull, z1 = 0ull;
            for (int k = 0; k < cnt; k += 2) {
                float4 e = ell4[k >> 1];
                uint2 r0 = *(const uint2*)(pbase + __float_as_int(e.y) * PSH);
                uint2 r1 = *(const uint2*)(pbase + __float_as_int(e.w) * PSH);
                u64 a0 = dup2(e.x), a1 = dup2(e.z);
                ffma2(z0, a0, h2_to_f2(r0.x)); ffma2(z1, a0, h2_to_f2(r0.y));
                ffma2(z0, a1, h2_to_f2(r1.x)); ffma2(z1, a1, h2_to_f2(r1.y));
            }

            float za, zb, zc, zd;
            unpack2(z0, za, zb); unpack2(z1, zc, zd);
            float4 o;
            o.x = 1.0f / (1.0f + __expf(-za));
            o.y = 1.0f / (1.0f + __expf(-zb));
            o.z = 1.0f / (1.0f + __expf(-zc));
            o.w = 1.0f / (1.0f + __expf(-zd));

            *(float4*)(out + (((size_t)b * TT + t0 + tl) * NN + n) * H2 + cq * 4) = o;
        }
    }
}

// ---------------------------------------------------------------------------
extern "C" void kernel_launch(void* const* d_in, const int* in_sizes, int n_in,
                              void* d_out, int out_size) {
    const float* x   = (const float*)d_in[0];   // [69, 32, 1024, 8]
    const float* adj = (const float*)d_in[1];   // [69, 69]
    const float* W1  = (const float*)d_in[2];   // [8, 32]
    const float* W2  = (const float*)d_in[3];   // [32, 16]
    float* out = (float*)d_out;                 // [32, 1024, 69, 16]

    prep_kernel<<<1, 256>>>(adj, W2);

    const int smem_bytes =
        768 * 4                     // W1 + W2t
        + NN * ELLS * 8             // ell float2
        + TW * NN * PSH * 2         // x|p alias region (fp16)
        + TW * NN * YS * 4          // y fp32
        + NN * 4;                   // cnt
    cudaFuncSetAttribute(gcn_kernel,
                         cudaFuncAttributeMaxDynamicSharedMemorySize, smem_bytes);
    gcn_kernel<<<(BB * TT) / TW, 256, smem_bytes>>>(x, W1, out);
}

// round 13
// speedup vs baseline: 1.9294x; 1.0669x over previous
#include <cuda_runtime.h>
#include <cuda_fp16.h>

#define NN  69
#define BB  32
#define TT  1024
#define FIN 8
#define H1  32
#define H2  16
#define TW  8      // t-positions per block
#define XSH 8      // x row stride in halves (16B rows): slab 1104B % 128 = 80 -> CF
#define YS  8      // y row stride in floats (32B rows): slab 2208B % 128 = 32 -> CF
#define PSH 16     // p row stride in halves (32B rows): slab 2208B % 128 = 32 -> CF
#define ELLS 48    // ELL row stride (entries); counts padded to mult of 4, max ~36
#define NTASK (TW * NN)   // 552

typedef unsigned long long u64;

// ---- f32x2 helpers (Blackwell packed fp32) --------------------------------
__device__ __forceinline__ void ffma2(u64& d, u64 a, u64 b) {
    asm("fma.rn.f32x2 %0, %1, %2, %0;" : "+l"(d) : "l"(a), "l"(b));
}
__device__ __forceinline__ u64 fadd2(u64 a, u64 b) {
    u64 r; asm("add.rn.f32x2 %0, %1, %2;" : "=l"(r) : "l"(a), "l"(b)); return r;
}
__device__ __forceinline__ u64 dup2(float a) {
    u64 r; asm("mov.b64 %0, {%1, %1};" : "=l"(r) : "f"(a)); return r;
}
__device__ __forceinline__ u64 pack2(float a, float b) {
    u64 r; asm("mov.b64 %0, {%1, %2};" : "=l"(r) : "f"(a), "f"(b)); return r;
}
__device__ __forceinline__ void unpack2(u64 v, float& a, float& b) {
    asm("mov.b64 {%0, %1}, %2;" : "=f"(a), "=f"(b) : "l"(v));
}
__device__ __forceinline__ u64 h2_to_f2(unsigned h) {
    float2 f = __half22float2(*(const __half2*)&h);
    return pack2(f.x, f.y);
}

// ---- scratch (no cudaMalloc allowed) --------------------------------------
__device__ float2 g_ell[NN * ELLS];    // (val, int_as_float(col)), padded to 4
__device__ int    g_cnt[NN];           // padded counts (multiple of 4)
__device__ float2 g_W2t[H2 * 16];      // [c][j2] = (W2[2j2][c], W2[2j2+1][c])

// ---------------------------------------------------------------------------
// Prep: adj_n = D^-1/2 (A+I) D^-1/2 packed ELL (cnt padded to 4) + W2t.
// ---------------------------------------------------------------------------
__global__ void prep_kernel(const float* __restrict__ adj,
                            const float* __restrict__ W2) {
    __shared__ float dis[NN];
    int tid = threadIdx.x;
    if (tid < NN) {
        float d = 1.0f;
        for (int m = 0; m < NN; m++) d += adj[tid * NN + m];
        dis[tid] = rsqrtf(d);
    }
    __syncthreads();
    if (tid < NN) {
        float di = dis[tid];
        int cnt = 0;
        for (int m = 0; m < NN && cnt < ELLS; m++) {
            float v = adj[tid * NN + m];
            if (m == tid) v += 1.0f;
            if (v != 0.0f) {
                g_ell[tid * ELLS + cnt] =
                    make_float2(v * di * dis[m], __int_as_float(m));
                cnt++;
            }
        }
        while ((cnt & 3) && cnt < ELLS) {   // pad to multiple of 4
            g_ell[tid * ELLS + cnt] = make_float2(0.0f, __int_as_float(0));
            cnt++;
        }
        g_cnt[tid] = cnt;
    }
    if (tid < H2 * 16) {
        int c = tid >> 4, j2 = tid & 15;
        g_W2t[tid] = make_float2(W2[(2 * j2) * H2 + c], W2[(2 * j2 + 1) * H2 + c]);
    }
}

// ---------------------------------------------------------------------------
// Fused GCN. fp16 gathered operands, fp32 f32x2 accumulation, neighbor loops
// unrolled x4 with dual accumulators (MLP 4, halved RAW-stall density).
// ---------------------------------------------------------------------------
__global__ __launch_bounds__(256, 2)
void gcn_kernel(const float* __restrict__ x,
                const float* __restrict__ W1,
                float* __restrict__ out) {
    extern __shared__ float sm[];
    float*  s_W1  = sm;                              // 1024B
    float2* s_W2t = (float2*)(sm + 256);             // 2048B
    float*  s_ell = sm + 768;                        // NN*ELLS float2 = 26496B
    __half* s_xp  = (__half*)(s_ell + NN * ELLS * 2);// x: 8832B | p: 17664B (alias)
    float*  s_y   = (float*)(s_xp + TW * NN * PSH);  // 17664B
    int*    s_cnt = (int*)(s_y + TW * NN * YS);      // 276B

    const int tid = threadIdx.x;
    const int bt0 = blockIdx.x * TW;
    const int b   = bt0 >> 10;
    const int t0  = bt0 & (TT - 1);

    // ---- cooperative smem fill ----
    s_W1[tid] = W1[tid];
    ((float2*)s_W2t)[tid] = g_W2t[tid];
    {
        const u64* ge = (const u64*)g_ell;
        u64* se = (u64*)s_ell;
        for (int i = tid; i < NN * ELLS; i += 256) se[i] = ge[i];
    }
    if (tid < NN) s_cnt[tid] = g_cnt[tid];
    {   // x slab: [n][b][t0+t][f] -> s_xp half [t][n][0..7] (stride XSH=8)
        const float4* xg = (const float4*)x;
        for (int i = tid; i < NN * TW * 2; i += 256) {
            int n = i >> 4;
            int r = i & 15;
            int t = r >> 1, h = r & 1;
            float4 v = xg[((size_t)(n * BB + b) * TT + t0 + t) * 2 + h];
            __half2 h0 = __floats2half2_rn(v.x, v.y);
            __half2 h1 = __floats2half2_rn(v.z, v.w);
            uint2 pkt = make_uint2(*(unsigned*)&h0, *(unsigned*)&h1);
            *(uint2*)(s_xp + (t * NN + n) * XSH + h * 4) = pkt;
        }
    }
    __syncthreads();

    const int w    = tid >> 5;
    const int lane = tid & 31;
    const int tl   = lane >> 2;      // t of this lane (0..7)
    const int cq   = lane & 3;       // chunk of this lane (0..3)

    // =========== Phase A: agg1. warp<->n; x4 unroll, dual accumulators =====
    {
        const __half* xbase = s_xp + tl * (NN * XSH) + cq * 2;
        float* ybase = s_y + tl * (NN * YS) + cq * 2;
        for (int n = w; n < NN; n += 8) {
            const float4* ell4 = (const float4*)(s_ell + n * (ELLS * 2));
            const int cnt = s_cnt[n];   // multiple of 4
            u64 acc0 = 0ull, acc1 = 0ull;
            for (int k = 0; k < cnt; k += 4) {
                float4 e0 = ell4[k >> 1];
                float4 e1 = ell4[(k >> 1) + 1];
                unsigned r0 = *(const unsigned*)(xbase + __float_as_int(e0.y) * XSH);
                unsigned r1 = *(const unsigned*)(xbase + __float_as_int(e0.w) * XSH);
                unsigned r2 = *(const unsigned*)(xbase + __float_as_int(e1.y) * XSH);
                unsigned r3 = *(const unsigned*)(xbase + __float_as_int(e1.w) * XSH);
                ffma2(acc0, dup2(e0.x), h2_to_f2(r0));
                ffma2(acc1, dup2(e0.z), h2_to_f2(r1));
                ffma2(acc0, dup2(e1.x), h2_to_f2(r2));
                ffma2(acc1, dup2(e1.z), h2_to_f2(r3));
            }
            *(u64*)(ybase + n * YS) = fadd2(acc0, acc1);
        }
    }
    __syncthreads();

    // =========== Phase A2: per (t,n): FC1 relu FC2 -> p fp16 (registers) ===
    #pragma unroll 1
    for (int r = 0; r < 3; r++) {
        int i = tid + (r << 8);
        if (i < NTASK) {
            int t = i / NN;
            int n = i - t * NN;

            const ulonglong2* yr = (const ulonglong2*)(s_y + (t * NN + n) * YS);
            ulonglong2 ya = yr[0], yb = yr[1];
            float ys[8];
            unpack2(ya.x, ys[0], ys[1]); unpack2(ya.y, ys[2], ys[3]);
            unpack2(yb.x, ys[4], ys[5]); unpack2(yb.y, ys[6], ys[7]);

            // ---- FC1: h[32] = y[8] @ W1 (broadcast weights) ----
            u64 h[16];
            #pragma unroll
            for (int q = 0; q < 16; q++) h[q] = 0ull;
            #pragma unroll
            for (int f = 0; f < FIN; f++) {
                u64 yd = dup2(ys[f]);
                const ulonglong2* wr = (const ulonglong2*)(s_W1 + f * H1);
                #pragma unroll
                for (int q = 0; q < 8; q++) {
                    ulonglong2 wv = wr[q];
                    ffma2(h[2 * q],     yd, wv.x);
                    ffma2(h[2 * q + 1], yd, wv.y);
                }
            }
            #pragma unroll
            for (int q = 0; q < 16; q++) {
                float a, bb2; unpack2(h[q], a, bb2);
                h[q] = pack2(fmaxf(a, 0.0f), fmaxf(bb2, 0.0f));
            }

            // ---- FC2: p[16] = h @ W2 ----
            float p[H2];
            #pragma unroll
            for (int c = 0; c < H2; c++) {
                u64 acc = 0ull;
                const ulonglong2* w2r = (const ulonglong2*)(s_W2t + c * 16);
                #pragma unroll
                for (int q = 0; q < 8; q++) {
                    ulonglong2 wv = w2r[q];
                    ffma2(acc, h[2 * q],     wv.x);
                    ffma2(acc, h[2 * q + 1], wv.y);
                }
                float a, bb2; unpack2(acc, a, bb2);
                p[c] = a + bb2;
            }

            // ---- store p as fp16 (2x 16B stores) ----
            unsigned hp[8];
            #pragma unroll
            for (int q = 0; q < 8; q++) {
                __half2 hv = __floats2half2_rn(p[2 * q], p[2 * q + 1]);
                hp[q] = *(unsigned*)&hv;
            }
            __half* pr = s_xp + (t * NN + n) * PSH;
            *(uint4*)(pr)     = make_uint4(hp[0], hp[1], hp[2], hp[3]);
            *(uint4*)(pr + 8) = make_uint4(hp[4], hp[5], hp[6], hp[7]);
        }
    }
    __syncthreads();

    // =========== Phase B: agg2 + sigmoid. x4 unroll, 4 accumulators ========
    {
        const __half* pbase = s_xp + tl * (NN * PSH) + cq * 4;
        for (int n = w; n < NN; n += 8) {
            const float4* ell4 = (const float4*)(s_ell + n * (ELLS * 2));
            const int cnt = s_cnt[n];
            u64 z0a = 0ull, z1a = 0ull, z0b = 0ull, z1b = 0ull;
            for (int k = 0; k < cnt; k += 4) {
                float4 e0 = ell4[k >> 1];
                float4 e1 = ell4[(k >> 1) + 1];
                uint2 r0 = *(const uint2*)(pbase + __float_as_int(e0.y) * PSH);
                uint2 r1 = *(const uint2*)(pbase + __float_as_int(e0.w) * PSH);
                uint2 r2 = *(const uint2*)(pbase + __float_as_int(e1.y) * PSH);
                uint2 r3 = *(const uint2*)(pbase + __float_as_int(e1.w) * PSH);
                u64 a0 = dup2(e0.x), a1 = dup2(e0.z);
                u64 a2 = dup2(e1.x), a3 = dup2(e1.z);
                ffma2(z0a, a0, h2_to_f2(r0.x)); ffma2(z1a, a0, h2_to_f2(r0.y));
                ffma2(z0b, a1, h2_to_f2(r1.x)); ffma2(z1b, a1, h2_to_f2(r1.y));
                ffma2(z0a, a2, h2_to_f2(r2.x)); ffma2(z1a, a2, h2_to_f2(r2.y));
                ffma2(z0b, a3, h2_to_f2(r3.x)); ffma2(z1b, a3, h2_to_f2(r3.y));
            }
            u64 z0 = fadd2(z0a, z0b);
            u64 z1 = fadd2(z1a, z1b);

            float za, zb, zc, zd;
            unpack2(z0, za, zb); unpack2(z1, zc, zd);
            float4 o;
            o.x = 1.0f / (1.0f + __expf(-za));
            o.y = 1.0f / (1.0f + __expf(-zb));
            o.z = 1.0f / (1.0f + __expf(-zc));
            o.w = 1.0f / (1.0f + __expf(-zd));

            *(float4*)(out + (((size_t)b * TT + t0 + tl) * NN + n) * H2 + cq * 4) = o;
        }
    }
}

// ---------------------------------------------------------------------------
extern "C" void kernel_launch(void* const* d_in, const int* in_sizes, int n_in,
                              void* d_out, int out_size) {
    const float* x   = (const float*)d_in[0];   // [69, 32, 1024, 8]
    const float* adj = (const float*)d_in[1];   // [69, 69]
    const float* W1  = (const float*)d_in[2];   // [8, 32]
    const float* W2  = (const float*)d_in[3];   // [32, 16]
    float* out = (float*)d_out;                 // [32, 1024, 69, 16]

    prep_kernel<<<1, 256>>>(adj, W2);

    const int smem_bytes =
        768 * 4                     // W1 + W2t
        + NN * ELLS * 8             // ell float2
        + TW * NN * PSH * 2         // x|p alias region (fp16)
        + TW * NN * YS * 4          // y fp32
        + NN * 4;                   // cnt
    cudaFuncSetAttribute(gcn_kernel,
                         cudaFuncAttributeMaxDynamicSharedMemorySize, smem_bytes);
    gcn_kernel<<<(BB * TT) / TW, 256, smem_bytes>>>(x, W1, out);
}

// round 15
// speedup vs baseline: 3.7743x; 1.9562x over previous
#include <cuda_runtime.h>
#include <cuda_fp16.h>

#define NN   69
#define BB   32
#define TT   1024
#define FIN  8
#define H1   32
#define H2   16
#define TW   8
#define NP   80      // padded node dim
#define ADJP 88      // adj row pitch (halves): 176B -> ldmatrix bank-distinct
#define XBP  72      // x slab row pitch (halves): 144B
#define YP   8       // y row pitch (halves): 16B
#define PP   136     // p row pitch (halves): 272B
#define MROWS 552    // TW*NN rows for the FC stage
#define MR_PAD 560

typedef unsigned u32;

// ---- smem offsets (halves unless noted) -----------------------------------
#define OFF_ADJ 0
#define OFF_XB  (NP * ADJP)                    // 7040
#define OFF_Y   (OFF_XB + NP * XBP)            // 12800
#define OFF_P   (OFF_Y + MR_PAD * YP)          // 17280
#define OFF_W1  (OFF_P + NP * PP)              // 28160
#define OFF_W2  (OFF_W1 + FIN * H1)            // 28416
#define SMEM_HALVES (OFF_W2 + H1 * H2)         // 28928 -> 57856 B

// ---- scratch (no cudaMalloc allowed) --------------------------------------
__device__ __half g_adjh[NP * ADJP];
__device__ __half g_W1h[FIN * H1];
__device__ __half g_W2h[H1 * H2];

// ---- PTX helpers ----------------------------------------------------------
__device__ __forceinline__ u32 cvta_s(const void* p) {
    return (u32)__cvta_generic_to_shared(p);
}
__device__ __forceinline__ void ldsm_x4(u32& r0, u32& r1, u32& r2, u32& r3, u32 a) {
    asm volatile("ldmatrix.sync.aligned.m8n8.x4.shared.b16 {%0,%1,%2,%3},[%4];"
                 : "=r"(r0), "=r"(r1), "=r"(r2), "=r"(r3) : "r"(a));
}
__device__ __forceinline__ void ldsm_x2(u32& r0, u32& r1, u32 a) {
    asm volatile("ldmatrix.sync.aligned.m8n8.x2.shared.b16 {%0,%1},[%2];"
                 : "=r"(r0), "=r"(r1) : "r"(a));
}
__device__ __forceinline__ void ldsm_x2t(u32& r0, u32& r1, u32 a) {
    asm volatile("ldmatrix.sync.aligned.m8n8.x2.trans.shared.b16 {%0,%1},[%2];"
                 : "=r"(r0), "=r"(r1) : "r"(a));
}
__device__ __forceinline__ void ldsm_x4t(u32& r0, u32& r1, u32& r2, u32& r3, u32 a) {
    asm volatile("ldmatrix.sync.aligned.m8n8.x4.trans.shared.b16 {%0,%1,%2,%3},[%4];"
                 : "=r"(r0), "=r"(r1), "=r"(r2), "=r"(r3) : "r"(a));
}
__device__ __forceinline__ void mma16816(float* c, u32 a0, u32 a1, u32 a2, u32 a3,
                                         u32 b0, u32 b1) {
    asm volatile(
        "mma.sync.aligned.m16n8k16.row.col.f32.f16.f16.f32 "
        "{%0,%1,%2,%3},{%4,%5,%6,%7},{%8,%9},{%0,%1,%2,%3};"
        : "+f"(c[0]), "+f"(c[1]), "+f"(c[2]), "+f"(c[3])
        : "r"(a0), "r"(a1), "r"(a2), "r"(a3), "r"(b0), "r"(b1));
}
__device__ __forceinline__ void mma1688(float* c, u32 a0, u32 a1, u32 b0) {
    asm volatile(
        "mma.sync.aligned.m16n8k8.row.col.f32.f16.f16.f32 "
        "{%0,%1,%2,%3},{%4,%5},{%6},{%0,%1,%2,%3};"
        : "+f"(c[0]), "+f"(c[1]), "+f"(c[2]), "+f"(c[3])
        : "r"(a0), "r"(a1), "r"(b0));
}
__device__ __forceinline__ u32 h2u(float a, float b) {
    __half2 h = __floats2half2_rn(a, b);
    return *(u32*)&h;
}
__device__ __forceinline__ float sigf(float z) {
    return 1.0f / (1.0f + __expf(-z));
}

// ---------------------------------------------------------------------------
// Prep: adj_n = D^-1/2 (A+I) D^-1/2, fp16 padded [80][88]; W1, W2 fp16.
// ---------------------------------------------------------------------------
__global__ void prep_kernel(const float* __restrict__ adj,
                            const float* __restrict__ W1,
                            const float* __restrict__ W2) {
    __shared__ float dis[NN];
    int tid = threadIdx.x;
    if (tid < NN) {
        float d = 1.0f;
        for (int m = 0; m < NN; m++) d += adj[tid * NN + m];
        dis[tid] = rsqrtf(d);
    }
    __syncthreads();
    if (tid < NP) {
        for (int m = 0; m < ADJP; m++) {
            float v = 0.0f;
            if (tid < NN && m < NN) {
                v = adj[tid * NN + m];
                if (m == tid) v += 1.0f;
                v *= dis[tid] * dis[m];
            }
            g_adjh[tid * ADJP + m] = __float2half(v);
        }
    }
    for (int i = tid; i < FIN * H1; i += 256) g_W1h[i] = __float2half(W1[i]);
    for (int i = tid; i < H1 * H2;  i += 256) g_W2h[i] = __float2half(W2[i]);  // BUGFIX: was tid<512 with 256 threads
}

// ---------------------------------------------------------------------------
// Tensor-core GCN: agg1 / FC1+relu+FC2 / agg2+sigmoid, all via mma.sync fp16.
// ---------------------------------------------------------------------------
__global__ __launch_bounds__(256, 3)
void gcn_kernel(const float* __restrict__ x,
                float* __restrict__ out) {
    extern __shared__ __half sh[];
    __half* s_adj = sh + OFF_ADJ;
    __half* s_xb  = sh + OFF_XB;
    __half* s_y   = sh + OFF_Y;
    __half* s_p   = sh + OFF_P;
    __half* s_W1  = sh + OFF_W1;
    __half* s_W2  = sh + OFF_W2;

    const int tid  = threadIdx.x;
    const int w    = tid >> 5;
    const int lane = tid & 31;
    const int g    = lane >> 2;     // group 0..7 (row within tile)
    const int tig  = lane & 3;      // thread-in-group 0..3

    const int bt0 = blockIdx.x * TW;
    const int b   = bt0 >> 10;
    const int t0  = bt0 & (TT - 1);

    // ================== cooperative smem fill ==============================
    for (int i = tid; i < NP * ADJP / 2; i += 256)
        ((u32*)s_adj)[i] = ((const u32*)g_adjh)[i];
    if (tid < 128) ((u32*)s_W1)[tid] = ((const u32*)g_W1h)[tid];
    ((u32*)s_W2)[tid] = ((const u32*)g_W2h)[tid];   // 256 u32 = 512 halves, exact
    // zero pads: xb rows 69..79, p rows 69..79 (cols 0..127), y rows 552..559
    for (int i = tid; i < (NP - NN) * XBP / 2; i += 256) {
        int r = i / (XBP / 2), c = i % (XBP / 2);
        ((u32*)(s_xb + (NN + r) * XBP))[c] = 0u;
    }
    for (int i = tid; i < (NP - NN) * 64; i += 256) {      // 11 rows x 128 halves
        int r = i >> 6, c = i & 63;
        ((u32*)(s_p + (NN + r) * PP))[c] = 0u;
    }
    if (tid < (MR_PAD - MROWS) * YP / 2)
        ((u32*)(s_y + MROWS * YP))[tid] = 0u;
    // x slab: x[n][b][t0+t][f] fp32 -> s_xb[n][t*8+f] fp16
    {
        const float4* xg = (const float4*)x;
        for (int i = tid; i < NN * TW * 2; i += 256) {
            int n = i >> 4;
            int r = i & 15;
            int t = r >> 1, h = r & 1;
            float4 v = xg[((size_t)(n * BB + b) * TT + t0 + t) * 2 + h];
            __half2 h0 = __floats2half2_rn(v.x, v.y);
            __half2 h1 = __floats2half2_rn(v.z, v.w);
            uint2 pkt = make_uint2(*(u32*)&h0, *(u32*)&h1);
            *(uint2*)(s_xb + n * XBP + t * 8 + h * 4) = pkt;
        }
    }
    __syncthreads();

    const u32 adj_b = cvta_s(s_adj);
    const u32 xb_b  = cvta_s(s_xb);
    const u32 y_b   = cvta_s(s_y);
    const u32 p_b   = cvta_s(s_p);

    // ================== Phase 1: agg1 = adj @ xslab ========================
    // C tiles: 5 m-tiles (n-node) x 8 n-tiles (t,f cols), k = 5 x 16
    for (int tile = w; tile < 40; tile += 8) {
        int mt = tile >> 3, nt = tile & 7;
        float c[4] = {0.f, 0.f, 0.f, 0.f};
        #pragma unroll
        for (int kt = 0; kt < 5; kt++) {
            u32 a0, a1, a2, a3, b0, b1;
            ldsm_x4(a0, a1, a2, a3,
                adj_b + ((mt * 16 + (lane & 15)) * ADJP + kt * 16 + (lane >> 4) * 8) * 2);
            ldsm_x2t(b0, b1,
                xb_b + ((kt * 16 + (lane & 15)) * XBP + nt * 8) * 2);
            mma16816(c, a0, a1, a2, a3, b0, b1);
        }
        // store y (fp16): row i = t*69 + n_node, cols f; t == nt here
        int r0 = mt * 16 + g;
        if (r0 < NN)
            *(u32*)(s_y + (nt * NN + r0) * YP + 2 * tig) = h2u(c[0], c[1]);
        int r1 = r0 + 8;
        if (r1 < NN)
            *(u32*)(s_y + (nt * NN + r1) * YP + 2 * tig) = h2u(c[2], c[3]);
    }
    __syncthreads();

    // ================== Phase 2: FC1 -> relu -> FC2 (frag-resident) ========
    u32 w1f[4];
    {
        u32 r0, r1, r2, r3;
        ldsm_x4t(r0, r1, r2, r3,
            cvta_s(s_W1) + ((lane & 7) * H1 + (lane >> 3) * 8) * 2);
        w1f[0] = r0; w1f[1] = r1; w1f[2] = r2; w1f[3] = r3;
    }
    u32 w2f[2][2][2];  // [kk][ct][reg]
    #pragma unroll
    for (int ct = 0; ct < 2; ct++) {
        u32 r0, r1, r2, r3;
        ldsm_x4t(r0, r1, r2, r3, cvta_s(s_W2) + (lane * H2 + ct * 8) * 2);
        w2f[0][ct][0] = r0; w2f[0][ct][1] = r1;
        w2f[1][ct][0] = r2; w2f[1][ct][1] = r3;
    }
    for (int mt = w; mt < 35; mt += 8) {
        u32 a0, a1;
        ldsm_x2(a0, a1, y_b + (mt * 16 + (lane & 15)) * YP * 2);
        float c1[4][4];
        #pragma unroll
        for (int j = 0; j < 4; j++) {
            c1[j][0] = c1[j][1] = c1[j][2] = c1[j][3] = 0.f;
            mma1688(c1[j], a0, a1, w1f[j]);
        }
        #pragma unroll
        for (int j = 0; j < 4; j++)
            #pragma unroll
            for (int q = 0; q < 4; q++) c1[j][q] = fmaxf(c1[j][q], 0.f);
        // C -> A fragment reuse (flash-attention trick)
        u32 A2[2][4];
        #pragma unroll
        for (int kk = 0; kk < 2; kk++) {
            A2[kk][0] = h2u(c1[2 * kk][0],     c1[2 * kk][1]);
            A2[kk][1] = h2u(c1[2 * kk][2],     c1[2 * kk][3]);
            A2[kk][2] = h2u(c1[2 * kk + 1][0], c1[2 * kk + 1][1]);
            A2[kk][3] = h2u(c1[2 * kk + 1][2], c1[2 * kk + 1][3]);
        }
        #pragma unroll
        for (int ct = 0; ct < 2; ct++) {
            float c2[4] = {0.f, 0.f, 0.f, 0.f};
            mma16816(c2, A2[0][0], A2[0][1], A2[0][2], A2[0][3],
                     w2f[0][ct][0], w2f[0][ct][1]);
            mma16816(c2, A2[1][0], A2[1][1], A2[1][2], A2[1][3],
                     w2f[1][ct][0], w2f[1][ct][1]);
            int i0 = mt * 16 + g;
            if (i0 < MROWS) {
                int t = i0 / NN, n = i0 - t * NN;
                *(u32*)(s_p + n * PP + t * 16 + ct * 8 + 2 * tig) = h2u(c2[0], c2[1]);
            }
            int i1 = i0 + 8;
            if (i1 < MROWS) {
                int t = i1 / NN, n = i1 - t * NN;
                *(u32*)(s_p + n * PP + t * 16 + ct * 8 + 2 * tig) = h2u(c2[2], c2[3]);
            }
        }
    }
    __syncthreads();

    // ================== Phase 3: agg2 = adj @ p, sigmoid, store ============
    // C tiles: 5 m-tiles x 16 n-tiles (t,c cols 128)
    for (int tile = w; tile < 80; tile += 8) {
        int mt = tile >> 4, ct = tile & 15;
        float c[4] = {0.f, 0.f, 0.f, 0.f};
        #pragma unroll
        for (int kt = 0; kt < 5; kt++) {
            u32 a0, a1, a2, a3, b0, b1;
            ldsm_x4(a0, a1, a2, a3,
                adj_b + ((mt * 16 + (lane & 15)) * ADJP + kt * 16 + (lane >> 4) * 8) * 2);
            ldsm_x2t(b0, b1,
                p_b + ((kt * 16 + (lane & 15)) * PP + ct * 8) * 2);
            mma16816(c, a0, a1, a2, a3, b0, b1);
        }
        int col = ct * 8 + 2 * tig;
        int t = col >> 4, cc = col & 15;
        size_t obase = ((size_t)(b * TT + t0 + t) * NN) * H2 + cc;
        int n0 = mt * 16 + g;
        if (n0 < NN) {
            float2 o = make_float2(sigf(c[0]), sigf(c[1]));
            *(float2*)(out + obase + (size_t)n0 * H2) = o;
        }
        int n1 = n0 + 8;
        if (n1 < NN) {
            float2 o = make_float2(sigf(c[2]), sigf(c[3]));
            *(float2*)(out + obase + (size_t)n1 * H2) = o;
        }
    }
}

// ---------------------------------------------------------------------------
extern "C" void kernel_launch(void* const* d_in, const int* in_sizes, int n_in,
                              void* d_out, int out_size) {
    const float* x   = (const float*)d_in[0];   // [69, 32, 1024, 8]
    const float* adj = (const float*)d_in[1];   // [69, 69]
    const float* W1  = (const float*)d_in[2];   // [8, 32]
    const float* W2  = (const float*)d_in[3];   // [32, 16]
    float* out = (float*)d_out;                 // [32, 1024, 69, 16]

    prep_kernel<<<1, 256>>>(adj, W1, W2);

    const int smem_bytes = SMEM_HALVES * 2;     // 57856
    cudaFuncSetAttribute(gcn_kernel,
                         cudaFuncAttributeMaxDynamicSharedMemorySize, smem_bytes);
    gcn_kernel<<<(BB * TT) / TW, 256, smem_bytes>>>(x, out);
}

// round 16
// speedup vs baseline: 4.4693x; 1.1841x over previous
#include <cuda_runtime.h>
#include <cuda_fp16.h>

#define NN   69
#define BB   32
#define TT   1024
#define FIN  8
#define H1   32
#define H2   16
#define TW   8
#define NP   80      // padded node dim
#define ADJP 88      // adj row pitch (halves): 176B -> ldmatrix bank-distinct
#define XBP  72      // x slab row pitch (halves): 144B
#define YP   8       // y row pitch (halves): 16B
#define PP   136     // p row pitch (halves): 272B
#define MROWS 552    // TW*NN rows for the FC stage
#define MR_PAD 560

typedef unsigned u32;

// ---- smem offsets (halves unless noted) -----------------------------------
#define OFF_ADJ 0
#define OFF_XB  (NP * ADJP)                    // 7040
#define OFF_Y   (OFF_XB + NP * XBP)            // 12800
#define OFF_P   (OFF_Y + MR_PAD * YP)          // 17280
#define OFF_W1  (OFF_P + NP * PP)              // 28160
#define OFF_W2  (OFF_W1 + FIN * H1)            // 28416
#define SMEM_HALVES (OFF_W2 + H1 * H2)         // 28928 -> 57856 B

// ---- scratch (no cudaMalloc allowed) --------------------------------------
__device__ __half g_adjh[NP * ADJP];
__device__ __half g_W1h[FIN * H1];
__device__ __half g_W2h[H1 * H2];

// ---- PTX helpers ----------------------------------------------------------
__device__ __forceinline__ u32 cvta_s(const void* p) {
    return (u32)__cvta_generic_to_shared(p);
}
__device__ __forceinline__ void ldsm_x4(u32& r0, u32& r1, u32& r2, u32& r3, u32 a) {
    asm volatile("ldmatrix.sync.aligned.m8n8.x4.shared.b16 {%0,%1,%2,%3},[%4];"
                 : "=r"(r0), "=r"(r1), "=r"(r2), "=r"(r3) : "r"(a));
}
__device__ __forceinline__ void ldsm_x2(u32& r0, u32& r1, u32 a) {
    asm volatile("ldmatrix.sync.aligned.m8n8.x2.shared.b16 {%0,%1},[%2];"
                 : "=r"(r0), "=r"(r1) : "r"(a));
}
__device__ __forceinline__ void ldsm_x2t(u32& r0, u32& r1, u32 a) {
    asm volatile("ldmatrix.sync.aligned.m8n8.x2.trans.shared.b16 {%0,%1},[%2];"
                 : "=r"(r0), "=r"(r1) : "r"(a));
}
__device__ __forceinline__ void ldsm_x4t(u32& r0, u32& r1, u32& r2, u32& r3, u32 a) {
    asm volatile("ldmatrix.sync.aligned.m8n8.x4.trans.shared.b16 {%0,%1,%2,%3},[%4];"
                 : "=r"(r0), "=r"(r1), "=r"(r2), "=r"(r3) : "r"(a));
}
__device__ __forceinline__ void mma16816(float* c, u32 a0, u32 a1, u32 a2, u32 a3,
                                         u32 b0, u32 b1) {
    asm volatile(
        "mma.sync.aligned.m16n8k16.row.col.f32.f16.f16.f32 "
        "{%0,%1,%2,%3},{%4,%5,%6,%7},{%8,%9},{%0,%1,%2,%3};"
        : "+f"(c[0]), "+f"(c[1]), "+f"(c[2]), "+f"(c[3])
        : "r"(a0), "r"(a1), "r"(a2), "r"(a3), "r"(b0), "r"(b1));
}
__device__ __forceinline__ void mma1688(float* c, u32 a0, u32 a1, u32 b0) {
    asm volatile(
        "mma.sync.aligned.m16n8k8.row.col.f32.f16.f16.f32 "
        "{%0,%1,%2,%3},{%4,%5},{%6},{%0,%1,%2,%3};"
        : "+f"(c[0]), "+f"(c[1]), "+f"(c[2]), "+f"(c[3])
        : "r"(a0), "r"(a1), "r"(b0));
}
__device__ __forceinline__ u32 h2u(float a, float b) {
    __half2 h = __floats2half2_rn(a, b);
    return *(u32*)&h;
}
__device__ __forceinline__ float sigf(float z) {
    return 1.0f / (1.0f + __expf(-z));
}

// ---------------------------------------------------------------------------
// Prep (parallelized): adj_n = D^-1/2 (A+I) D^-1/2 fp16 [80][88]; W1, W2 fp16.
// ---------------------------------------------------------------------------
__global__ void prep_kernel(const float* __restrict__ adj,
                            const float* __restrict__ W1,
                            const float* __restrict__ W2) {
    __shared__ float dis[NN];
    const int tid  = threadIdx.x;
    const int w    = tid >> 5;
    const int lane = tid & 31;

    // warp-per-row degree reduction
    for (int n = w; n < NN; n += 8) {
        float s = 0.0f;
        for (int m = lane; m < NN; m += 32) s += adj[n * NN + m];
        #pragma unroll
        for (int o = 16; o; o >>= 1) s += __shfl_xor_sync(0xffffffffu, s, o);
        if (lane == 0) dis[n] = rsqrtf(s + 1.0f);
    }
    __syncthreads();

    // flat parallel conversion (27.5 independent loads/thread, MLP-covered)
    for (int i = tid; i < NP * ADJP; i += 256) {
        int r = i / ADJP, m = i - r * ADJP;
        float v = 0.0f;
        if (r < NN && m < NN) {
            v = adj[r * NN + m];
            if (m == r) v += 1.0f;
            v *= dis[r] * dis[m];
        }
        g_adjh[i] = __float2half(v);
    }
    for (int i = tid; i < FIN * H1; i += 256) g_W1h[i] = __float2half(W1[i]);
    for (int i = tid; i < H1 * H2;  i += 256) g_W2h[i] = __float2half(W2[i]);
}

// ---------------------------------------------------------------------------
// Tensor-core GCN with adjacency A-fragment caching (mt-major warp tiling).
// ---------------------------------------------------------------------------
__global__ __launch_bounds__(256, 3)
void gcn_kernel(const float* __restrict__ x,
                float* __restrict__ out) {
    extern __shared__ __half sh[];
    __half* s_adj = sh + OFF_ADJ;
    __half* s_xb  = sh + OFF_XB;
    __half* s_y   = sh + OFF_Y;
    __half* s_p   = sh + OFF_P;
    __half* s_W1  = sh + OFF_W1;
    __half* s_W2  = sh + OFF_W2;

    const int tid  = threadIdx.x;
    const int w    = tid >> 5;
    const int lane = tid & 31;
    const int g    = lane >> 2;     // group 0..7 (row within tile)
    const int tig  = lane & 3;      // thread-in-group 0..3

    const int bt0 = blockIdx.x * TW;
    const int b   = bt0 >> 10;
    const int t0  = bt0 & (TT - 1);

    // ================== cooperative smem fill ==============================
    for (int i = tid; i < NP * ADJP / 8; i += 256)       // uint4 adj copy
        ((uint4*)s_adj)[i] = ((const uint4*)g_adjh)[i];
    if (tid < 128) ((u32*)s_W1)[tid] = ((const u32*)g_W1h)[tid];
    ((u32*)s_W2)[tid] = ((const u32*)g_W2h)[tid];        // 256 u32 = 512 halves
    // zero pads: xb rows 69..79, p rows 69..79 (cols 0..127), y rows 552..559
    for (int i = tid; i < (NP - NN) * XBP / 2; i += 256) {
        int r = i / (XBP / 2), c = i % (XBP / 2);
        ((u32*)(s_xb + (NN + r) * XBP))[c] = 0u;
    }
    for (int i = tid; i < (NP - NN) * 64; i += 256) {    // 11 rows x 128 halves
        int r = i >> 6, c = i & 63;
        ((u32*)(s_p + (NN + r) * PP))[c] = 0u;
    }
    if (tid < (MR_PAD - MROWS) * YP / 2)
        ((u32*)(s_y + MROWS * YP))[tid] = 0u;
    // x slab: x[n][b][t0+t][f] fp32 -> s_xb[n][t*8+f] fp16
    {
        const float4* xg = (const float4*)x;
        for (int i = tid; i < NN * TW * 2; i += 256) {
            int n = i >> 4;
            int r = i & 15;
            int t = r >> 1, h = r & 1;
            float4 v = xg[((size_t)(n * BB + b) * TT + t0 + t) * 2 + h];
            __half2 h0 = __floats2half2_rn(v.x, v.y);
            __half2 h1 = __floats2half2_rn(v.z, v.w);
            uint2 pkt = make_uint2(*(u32*)&h0, *(u32*)&h1);
            *(uint2*)(s_xb + n * XBP + t * 8 + h * 4) = pkt;
        }
    }
    __syncthreads();

    const u32 adj_b = cvta_s(s_adj);
    const u32 xb_b  = cvta_s(s_xb);
    const u32 y_b   = cvta_s(s_y);
    const u32 p_b   = cvta_s(s_p);

    // ================== Phase 1: agg1 = adj @ xslab ========================
    // tiles idx = mt*8 + nt (mt-major); warp range [w*5, w*5+5); A cached.
    {
        int mtCur = -1;
        u32 af[5][4];
        for (int idx = w * 5; idx < w * 5 + 5; idx++) {
            int mt = idx >> 3, nt = idx & 7;
            if (mt != mtCur) {
                mtCur = mt;
                #pragma unroll
                for (int kt = 0; kt < 5; kt++)
                    ldsm_x4(af[kt][0], af[kt][1], af[kt][2], af[kt][3],
                        adj_b + ((mt * 16 + (lane & 15)) * ADJP
                                 + kt * 16 + (lane >> 4) * 8) * 2);
            }
            float c[4] = {0.f, 0.f, 0.f, 0.f};
            #pragma unroll
            for (int kt = 0; kt < 5; kt++) {
                u32 b0, b1;
                ldsm_x2t(b0, b1,
                    xb_b + ((kt * 16 + (lane & 15)) * XBP + nt * 8) * 2);
                mma16816(c, af[kt][0], af[kt][1], af[kt][2], af[kt][3], b0, b1);
            }
            int r0 = mt * 16 + g;
            if (r0 < NN)
                *(u32*)(s_y + (nt * NN + r0) * YP + 2 * tig) = h2u(c[0], c[1]);
            int r1 = r0 + 8;
            if (r1 < NN)
                *(u32*)(s_y + (nt * NN + r1) * YP + 2 * tig) = h2u(c[2], c[3]);
        }
    }
    __syncthreads();

    // ================== Phase 2: FC1 -> relu -> FC2 (frag-resident) ========
    {
        u32 w1f[4];
        {
            u32 r0, r1, r2, r3;
            ldsm_x4t(r0, r1, r2, r3,
                cvta_s(s_W1) + ((lane & 7) * H1 + (lane >> 3) * 8) * 2);
            w1f[0] = r0; w1f[1] = r1; w1f[2] = r2; w1f[3] = r3;
        }
        u32 w2f[2][2][2];  // [kk][ct][reg]
        #pragma unroll
        for (int ct = 0; ct < 2; ct++) {
            u32 r0, r1, r2, r3;
            ldsm_x4t(r0, r1, r2, r3, cvta_s(s_W2) + (lane * H2 + ct * 8) * 2);
            w2f[0][ct][0] = r0; w2f[0][ct][1] = r1;
            w2f[1][ct][0] = r2; w2f[1][ct][1] = r3;
        }
        for (int mt = w; mt < 35; mt += 8) {
            u32 a0, a1;
            ldsm_x2(a0, a1, y_b + (mt * 16 + (lane & 15)) * YP * 2);
            float c1[4][4];
            #pragma unroll
            for (int j = 0; j < 4; j++) {
                c1[j][0] = c1[j][1] = c1[j][2] = c1[j][3] = 0.f;
                mma1688(c1[j], a0, a1, w1f[j]);
            }
            #pragma unroll
            for (int j = 0; j < 4; j++)
                #pragma unroll
                for (int q = 0; q < 4; q++) c1[j][q] = fmaxf(c1[j][q], 0.f);
            // C -> A fragment reuse
            u32 A2[2][4];
            #pragma unroll
            for (int kk = 0; kk < 2; kk++) {
                A2[kk][0] = h2u(c1[2 * kk][0],     c1[2 * kk][1]);
                A2[kk][1] = h2u(c1[2 * kk][2],     c1[2 * kk][3]);
                A2[kk][2] = h2u(c1[2 * kk + 1][0], c1[2 * kk + 1][1]);
                A2[kk][3] = h2u(c1[2 * kk + 1][2], c1[2 * kk + 1][3]);
            }
            #pragma unroll
            for (int ct = 0; ct < 2; ct++) {
                float c2[4] = {0.f, 0.f, 0.f, 0.f};
                mma16816(c2, A2[0][0], A2[0][1], A2[0][2], A2[0][3],
                         w2f[0][ct][0], w2f[0][ct][1]);
                mma16816(c2, A2[1][0], A2[1][1], A2[1][2], A2[1][3],
                         w2f[1][ct][0], w2f[1][ct][1]);
                int i0 = mt * 16 + g;
                if (i0 < MROWS) {
                    int t = i0 / NN, n = i0 - t * NN;
                    *(u32*)(s_p + n * PP + t * 16 + ct * 8 + 2 * tig) = h2u(c2[0], c2[1]);
                }
                int i1 = i0 + 8;
                if (i1 < MROWS) {
                    int t = i1 / NN, n = i1 - t * NN;
                    *(u32*)(s_p + n * PP + t * 16 + ct * 8 + 2 * tig) = h2u(c2[2], c2[3]);
                }
            }
        }
    }
    __syncthreads();

    // ================== Phase 3: agg2 = adj @ p, sigmoid, store ============
    // tiles idx = mt*16 + ct (mt-major); warp range [w*10, w*10+10); A cached.
    {
        int mtCur = -1;
        u32 af[5][4];
        for (int idx = w * 10; idx < w * 10 + 10; idx++) {
            int mt = idx >> 4, ct = idx & 15;
            if (mt != mtCur) {
                mtCur = mt;
                #pragma unroll
                for (int kt = 0; kt < 5; kt++)
                    ldsm_x4(af[kt][0], af[kt][1], af[kt][2], af[kt][3],
                        adj_b + ((mt * 16 + (lane & 15)) * ADJP
                                 + kt * 16 + (lane >> 4) * 8) * 2);
            }
            float c[4] = {0.f, 0.f, 0.f, 0.f};
            #pragma unroll
            for (int kt = 0; kt < 5; kt++) {
                u32 b0, b1;
                ldsm_x2t(b0, b1,
                    p_b + ((kt * 16 + (lane & 15)) * PP + ct * 8) * 2);
                mma16816(c, af[kt][0], af[kt][1], af[kt][2], af[kt][3], b0, b1);
            }
            int col = ct * 8 + 2 * tig;
            int t = col >> 4, cc = col & 15;
            size_t obase = ((size_t)(b * TT + t0 + t) * NN) * H2 + cc;
            int n0 = mt * 16 + g;
            if (n0 < NN) {
                float2 o = make_float2(sigf(c[0]), sigf(c[1]));
                *(float2*)(out + obase + (size_t)n0 * H2) = o;
            }
            int n1 = n0 + 8;
            if (n1 < NN) {
                float2 o = make_float2(sigf(c[2]), sigf(c[3]));
                *(float2*)(out + obase + (size_t)n1 * H2) = o;
            }
        }
    }
}

// ---------------------------------------------------------------------------
extern "C" void kernel_launch(void* const* d_in, const int* in_sizes, int n_in,
                              void* d_out, int out_size) {
    const float* x   = (const float*)d_in[0];   // [69, 32, 1024, 8]
    const float* adj = (const float*)d_in[1];   // [69, 69]
    const float* W1  = (const float*)d_in[2];   // [8, 32]
    const float* W2  = (const float*)d_in[3];   // [32, 16]
    float* out = (float*)d_out;                 // [32, 1024, 69, 16]

    prep_kernel<<<1, 256>>>(adj, W1, W2);

    const int smem_bytes = SMEM_HALVES * 2;     // 57856
    cudaFuncSetAttribute(gcn_kernel,
                         cudaFuncAttributeMaxDynamicSharedMemorySize, smem_bytes);
    gcn_kernel<<<(BB * TT) / TW, 256, smem_bytes>>>(x, out);
}

// round 17
// speedup vs baseline: 5.1941x; 1.1622x over previous
#include <cuda_runtime.h>
#include <cuda_fp16.h>

#define NN   69
#define BB   32
#define TT   1024
#define FIN  8
#define H1   32
#define H2   16
#define TW   8
#define NP   80      // padded node dim
#define ADJP 88      // adj row pitch (halves): 176B -> ldmatrix bank-distinct
#define XBP  72      // x slab row pitch (halves): 144B
#define YP   8       // y row pitch (halves): 16B
#define PP   136     // p row pitch (halves): 272B
#define MROWS 552    // TW*NN rows for the FC stage
#define MR_PAD 560

typedef unsigned u32;

// ---- smem offsets (halves) -------------------------------------------------
#define OFF_ADJ 0
#define OFF_XB  (NP * ADJP)                    // 7040
#define OFF_Y   (OFF_XB + NP * XBP)            // 12800
#define OFF_P   (OFF_Y + MR_PAD * YP)          // 17280
#define SMEM_HALVES (OFF_P + NP * PP)          // 28160 -> 56320 B (4 blocks/SM)

// ---- scratch (no cudaMalloc allowed) --------------------------------------
__device__ float  g_dis[NN];
__device__ __half g_adjh[NP * ADJP];

// ---- PTX helpers ----------------------------------------------------------
__device__ __forceinline__ u32 cvta_s(const void* p) {
    return (u32)__cvta_generic_to_shared(p);
}
__device__ __forceinline__ void ldsm_x4(u32& r0, u32& r1, u32& r2, u32& r3, u32 a) {
    asm volatile("ldmatrix.sync.aligned.m8n8.x4.shared.b16 {%0,%1,%2,%3},[%4];"
                 : "=r"(r0), "=r"(r1), "=r"(r2), "=r"(r3) : "r"(a));
}
__device__ __forceinline__ void ldsm_x2(u32& r0, u32& r1, u32 a) {
    asm volatile("ldmatrix.sync.aligned.m8n8.x2.shared.b16 {%0,%1},[%2];"
                 : "=r"(r0), "=r"(r1) : "r"(a));
}
__device__ __forceinline__ void ldsm_x2t(u32& r0, u32& r1, u32 a) {
    asm volatile("ldmatrix.sync.aligned.m8n8.x2.trans.shared.b16 {%0,%1},[%2];"
                 : "=r"(r0), "=r"(r1) : "r"(a));
}
__device__ __forceinline__ void mma16816(float* c, u32 a0, u32 a1, u32 a2, u32 a3,
                                         u32 b0, u32 b1) {
    asm volatile(
        "mma.sync.aligned.m16n8k16.row.col.f32.f16.f16.f32 "
        "{%0,%1,%2,%3},{%4,%5,%6,%7},{%8,%9},{%0,%1,%2,%3};"
        : "+f"(c[0]), "+f"(c[1]), "+f"(c[2]), "+f"(c[3])
        : "r"(a0), "r"(a1), "r"(a2), "r"(a3), "r"(b0), "r"(b1));
}
__device__ __forceinline__ void mma1688(float* c, u32 a0, u32 a1, u32 b0) {
    asm volatile(
        "mma.sync.aligned.m16n8k8.row.col.f32.f16.f16.f32 "
        "{%0,%1,%2,%3},{%4,%5},{%6},{%0,%1,%2,%3};"
        : "+f"(c[0]), "+f"(c[1]), "+f"(c[2]), "+f"(c[3])
        : "r"(a0), "r"(a1), "r"(b0));
}
__device__ __forceinline__ u32 h2u(float a, float b) {
    __half2 h = __floats2half2_rn(a, b);
    return *(u32*)&h;
}
__device__ __forceinline__ float sigf(float z) {
    return 1.0f / (1.0f + __expf(-z));
}

// ---------------------------------------------------------------------------
// Prep, split for parallelism: degrees (1 block), then conversion (28 blocks).
// ---------------------------------------------------------------------------
__global__ void prep_deg(const float* __restrict__ adj) {
    const int w = threadIdx.x >> 5, lane = threadIdx.x & 31;
    for (int n = w; n < NN; n += 32) {
        float s = 0.0f;
        for (int m = lane; m < NN; m += 32) s += adj[n * NN + m];
        #pragma unroll
        for (int o = 16; o; o >>= 1) s += __shfl_xor_sync(0xffffffffu, s, o);
        if (lane == 0) g_dis[n] = rsqrtf(s + 1.0f);
    }
}
__global__ void prep_cvt(const float* __restrict__ adj) {
    int i = blockIdx.x * blockDim.x + threadIdx.x;
    if (i < NP * ADJP) {
        int r = i / ADJP, m = i - r * ADJP;
        float v = 0.0f;
        if (r < NN && m < NN) {
            v = adj[r * NN + m];
            if (m == r) v += 1.0f;
            v *= g_dis[r] * g_dis[m];
        }
        g_adjh[i] = __float2half(v);
    }
}

// ---------------------------------------------------------------------------
// Tensor-core GCN; W fragments per-lane from global; 4 blocks/SM.
// ---------------------------------------------------------------------------
__global__ __launch_bounds__(256, 4)
void gcn_kernel(const float* __restrict__ x,
                const float* __restrict__ W1g,
                const float* __restrict__ W2g,
                float* __restrict__ out) {
    extern __shared__ __half sh[];
    __half* s_adj = sh + OFF_ADJ;
    __half* s_xb  = sh + OFF_XB;
    __half* s_y   = sh + OFF_Y;
    __half* s_p   = sh + OFF_P;

    const int tid  = threadIdx.x;
    const int w    = tid >> 5;
    const int lane = tid & 31;
    const int g    = lane >> 2;     // group 0..7
    const int tig  = lane & 3;      // thread-in-group 0..3

    const int bt0 = blockIdx.x * TW;
    const int b   = bt0 >> 10;
    const int t0  = bt0 & (TT - 1);

    // ================== cooperative smem fill ==============================
    for (int i = tid; i < NP * ADJP / 8; i += 256)       // uint4 adj copy
        ((uint4*)s_adj)[i] = ((const uint4*)g_adjh)[i];
    // zero pads: xb rows 69..79, p rows 69..79 (cols 0..127), y rows 552..559
    for (int i = tid; i < (NP - NN) * XBP / 2; i += 256) {
        int r = i / (XBP / 2), c = i % (XBP / 2);
        ((u32*)(s_xb + (NN + r) * XBP))[c] = 0u;
    }
    for (int i = tid; i < (NP - NN) * 64; i += 256) {    // 11 rows x 128 halves
        int r = i >> 6, c = i & 63;
        ((u32*)(s_p + (NN + r) * PP))[c] = 0u;
    }
    if (tid < (MR_PAD - MROWS) * YP / 2)
        ((u32*)(s_y + MROWS * YP))[tid] = 0u;
    // x slab: x[n][b][t0+t][f] fp32 -> s_xb[n][t*8+f] fp16
    {
        const float4* xg = (const float4*)x;
        for (int i = tid; i < NN * TW * 2; i += 256) {
            int n = i >> 4;
            int r = i & 15;
            int t = r >> 1, h = r & 1;
            float4 v = xg[((size_t)(n * BB + b) * TT + t0 + t) * 2 + h];
            __half2 h0 = __floats2half2_rn(v.x, v.y);
            __half2 h1 = __floats2half2_rn(v.z, v.w);
            uint2 pkt = make_uint2(*(u32*)&h0, *(u32*)&h1);
            *(uint2*)(s_xb + n * XBP + t * 8 + h * 4) = pkt;
        }
    }
    __syncthreads();

    const u32 adj_b = cvta_s(s_adj);
    const u32 xb_b  = cvta_s(s_xb);
    const u32 y_b   = cvta_s(s_y);
    const u32 p_b   = cvta_s(s_p);

    // ================== Phase 1: agg1 = adj @ xslab ========================
    // tiles idx = mt*8 + nt (mt-major); warp range [w*5, w*5+5); A cached.
    {
        int mtCur = -1;
        u32 af[5][4];
        for (int idx = w * 5; idx < w * 5 + 5; idx++) {
            int mt = idx >> 3, nt = idx & 7;
            if (mt != mtCur) {
                mtCur = mt;
                #pragma unroll
                for (int kt = 0; kt < 5; kt++)
                    ldsm_x4(af[kt][0], af[kt][1], af[kt][2], af[kt][3],
                        adj_b + ((mt * 16 + (lane & 15)) * ADJP
                                 + kt * 16 + (lane >> 4) * 8) * 2);
            }
            float c[4] = {0.f, 0.f, 0.f, 0.f};
            #pragma unroll
            for (int kt = 0; kt < 5; kt++) {
                u32 b0, b1;
                ldsm_x2t(b0, b1,
                    xb_b + ((kt * 16 + (lane & 15)) * XBP + nt * 8) * 2);
                mma16816(c, af[kt][0], af[kt][1], af[kt][2], af[kt][3], b0, b1);
            }
            int r0 = mt * 16 + g;
            if (r0 < NN)
                *(u32*)(s_y + (nt * NN + r0) * YP + 2 * tig) = h2u(c[0], c[1]);
            int r1 = r0 + 8;
            if (r1 < NN)
                *(u32*)(s_y + (nt * NN + r1) * YP + 2 * tig) = h2u(c[2], c[3]);
        }
    }
    __syncthreads();

    // ================== Phase 2: FC1 -> relu -> FC2 (frag-resident) ========
    {
        // W fragments per-lane from global fp32 (PTX B-fragment layouts):
        // m16n8k8 B: b0 = {B[2*tig][g], B[2*tig+1][g]}
        u32 w1f[4];
        #pragma unroll
        for (int j = 0; j < 4; j++)
            w1f[j] = h2u(W1g[(2 * tig) * H1 + j * 8 + g],
                         W1g[(2 * tig + 1) * H1 + j * 8 + g]);
        // m16n8k16 B: b0 = {B[2*tig][g], B[2*tig+1][g]}, b1 = rows +8
        u32 w2f[2][2][2];  // [kk][ct][reg]
        #pragma unroll
        for (int kk = 0; kk < 2; kk++)
            #pragma unroll
            for (int ct = 0; ct < 2; ct++) {
                int rb = kk * 16 + 2 * tig;
                w2f[kk][ct][0] = h2u(W2g[rb * H2 + ct * 8 + g],
                                     W2g[(rb + 1) * H2 + ct * 8 + g]);
                w2f[kk][ct][1] = h2u(W2g[(rb + 8) * H2 + ct * 8 + g],
                                     W2g[(rb + 9) * H2 + ct * 8 + g]);
            }
        for (int mt = w; mt < 35; mt += 8) {
            u32 a0, a1;
            ldsm_x2(a0, a1, y_b + (mt * 16 + (lane & 15)) * YP * 2);
            float c1[4][4];
            #pragma unroll
            for (int j = 0; j < 4; j++) {
                c1[j][0] = c1[j][1] = c1[j][2] = c1[j][3] = 0.f;
                mma1688(c1[j], a0, a1, w1f[j]);
            }
            #pragma unroll
            for (int j = 0; j < 4; j++)
                #pragma unroll
                for (int q = 0; q < 4; q++) c1[j][q] = fmaxf(c1[j][q], 0.f);
            // C -> A fragment reuse
            u32 A2[2][4];
            #pragma unroll
            for (int kk = 0; kk < 2; kk++) {
                A2[kk][0] = h2u(c1[2 * kk][0],     c1[2 * kk][1]);
                A2[kk][1] = h2u(c1[2 * kk][2],     c1[2 * kk][3]);
                A2[kk][2] = h2u(c1[2 * kk + 1][0], c1[2 * kk + 1][1]);
                A2[kk][3] = h2u(c1[2 * kk + 1][2], c1[2 * kk + 1][3]);
            }
            #pragma unroll
            for (int ct = 0; ct < 2; ct++) {
                float c2[4] = {0.f, 0.f, 0.f, 0.f};
                mma16816(c2, A2[0][0], A2[0][1], A2[0][2], A2[0][3],
                         w2f[0][ct][0], w2f[0][ct][1]);
                mma16816(c2, A2[1][0], A2[1][1], A2[1][2], A2[1][3],
                         w2f[1][ct][0], w2f[1][ct][1]);
                int i0 = mt * 16 + g;
                if (i0 < MROWS) {
                    int t = i0 / NN, n = i0 - t * NN;
                    *(u32*)(s_p + n * PP + t * 16 + ct * 8 + 2 * tig) = h2u(c2[0], c2[1]);
                }
                int i1 = i0 + 8;
                if (i1 < MROWS) {
                    int t = i1 / NN, n = i1 - t * NN;
                    *(u32*)(s_p + n * PP + t * 16 + ct * 8 + 2 * tig) = h2u(c2[2], c2[3]);
                }
            }
        }
    }
    __syncthreads();

    // ================== Phase 3: agg2 = adj @ p, sigmoid, store ============
    // tiles idx = mt*16 + ct (mt-major); warp range [w*10, w*10+10); A cached.
    {
        int mtCur = -1;
        u32 af[5][4];
        for (int idx = w * 10; idx < w * 10 + 10; idx++) {
            int mt = idx >> 4, ct = idx & 15;
            if (mt != mtCur) {
                mtCur = mt;
                #pragma unroll
                for (int kt = 0; kt < 5; kt++)
                    ldsm_x4(af[kt][0], af[kt][1], af[kt][2], af[kt][3],
                        adj_b + ((mt * 16 + (lane & 15)) * ADJP
                                 + kt * 16 + (lane >> 4) * 8) * 2);
            }
            float c[4] = {0.f, 0.f, 0.f, 0.f};
            #pragma unroll
            for (int kt = 0; kt < 5; kt++) {
                u32 b0, b1;
                ldsm_x2t(b0, b1,
                    p_b + ((kt * 16 + (lane & 15)) * PP + ct * 8) * 2);
                mma16816(c, af[kt][0], af[kt][1], af[kt][2], af[kt][3], b0, b1);
            }
            int col = ct * 8 + 2 * tig;
            int t = col >> 4, cc = col & 15;
            size_t obase = ((size_t)(b * TT + t0 + t) * NN) * H2 + cc;
            int n0 = mt * 16 + g;
            if (n0 < NN) {
                float2 o = make_float2(sigf(c[0]), sigf(c[1]));
                *(float2*)(out + obase + (size_t)n0 * H2) = o;
            }
            int n1 = n0 + 8;
            if (n1 < NN) {
                float2 o = make_float2(sigf(c[2]), sigf(c[3]));
                *(float2*)(out + obase + (size_t)n1 * H2) = o;
            }
        }
    }
}

// ---------------------------------------------------------------------------
extern "C" void kernel_launch(void* const* d_in, const int* in_sizes, int n_in,
                              void* d_out, int out_size) {
    const float* x   = (const float*)d_in[0];   // [69, 32, 1024, 8]
    const float* adj = (const float*)d_in[1];   // [69, 69]
    const float* W1  = (const float*)d_in[2];   // [8, 32]
    const float* W2  = (const float*)d_in[3];   // [32, 16]
    float* out = (float*)d_out;                 // [32, 1024, 69, 16]

    prep_deg<<<1, 1024>>>(adj);
    prep_cvt<<<(NP * ADJP + 255) / 256, 256>>>(adj);

    const int smem_bytes = SMEM_HALVES * 2;     // 56320
    cudaFuncSetAttribute(gcn_kernel,
                         cudaFuncAttributeMaxDynamicSharedMemorySize, smem_bytes);
    gcn_kernel<<<(BB * TT) / TW, 256, smem_bytes>>>(x, W1, W2, out);
}